// round 11
// baseline (speedup 1.0000x reference)
#include <cuda_runtime.h>
#include <cstdint>

#define HID 256
#define H4  64            // HID/4 float4 per row
#define NB  1024          // number of graphs
#define EPS 1e-5f
#define MLP_BLOCKS 128
#define POOL_BLOCKS 2048

// scratch (allocation-free rule: static __device__ globals)
__device__ float g_hpool[NB * HID];
__device__ float g_h1[NB * HID];
__device__ float g_sum[HID];
__device__ float g_sumsq[HID];
__device__ int   g_barrier;

// ---------------------------------------------------------------------------
// 0) init: zero hpool (atomic accumulation target), BN stats, barrier.
// ---------------------------------------------------------------------------
__global__ __launch_bounds__(256) void init_kernel(
    float* __restrict__ hpool, float* __restrict__ gsum,
    float* __restrict__ gsumsq, int* __restrict__ barrier)
{
    int i = blockIdx.x * 256 + threadIdx.x;
    reinterpret_cast<float4*>(hpool)[i] = make_float4(0.f, 0.f, 0.f, 0.f);
    if (blockIdx.x == 0) {
        gsum[threadIdx.x] = 0.f;
        gsumsq[threadIdx.x] = 0.f;
        if (threadIdx.x == 0) *barrier = 0;
    }
}

// ---------------------------------------------------------------------------
// 1) chunked segmented reduction (pool), BRANCH-FREE inner loop.
//    Warp 0 pre-scans the chunk's (sorted) bidx with ballot/popc into an
//    ordered boundary list; each sub-segment is then a pure streaming
//    accumulate (unroll-8, front-batched __ldcs) + one atomicAdd flush.
// ---------------------------------------------------------------------------
__global__ __launch_bounds__(256) void pool_kernel(
    const float* __restrict__ x, const int* __restrict__ bidx,
    float* __restrict__ hpool, int n)
{
    __shared__ int bnd[260];
    __shared__ int nbnd_s;

    int t = threadIdx.x;
    int chunk = (n + POOL_BLOCKS - 1) / POOL_BLOCKS;
    int r0 = blockIdx.x * chunk;
    int r1 = min(r0 + chunk, n);
    if (r0 >= r1) return;

    // ---- warp 0: ordered boundary scan of bidx[r0..r1) ----
    if (t < 32) {
        int nb = 0;
        for (int base = r0; base < r1; base += 32) {
            int row = base + t;
            bool pred = false;
            if (row < r1 && row > r0)
                pred = (__ldg(&bidx[row]) != __ldg(&bidx[row - 1]));
            unsigned mask = __ballot_sync(0xffffffffu, pred);
            int idx = nb + __popc(mask & ((1u << t) - 1u));
            if (pred) bnd[idx] = row;
            nb += __popc(mask);
        }
        if (t == 0) nbnd_s = nb;
    }
    __syncthreads();
    int nbnd = nbnd_s;

    int c4 = t & 63;        // float4 column 0..63
    int rg = t >> 6;        // row group 0..3
    const float4* x4 = reinterpret_cast<const float4*>(x);

    int s_lo = r0;
    for (int k = 0; k <= nbnd; k++) {
        int s_hi = (k < nbnd) ? bnd[k] : r1;
        int g = __ldg(&bidx[s_lo]);

        float4 acc0 = make_float4(0.f, 0.f, 0.f, 0.f);
        float4 acc1 = make_float4(0.f, 0.f, 0.f, 0.f);
        float4 acc2 = make_float4(0.f, 0.f, 0.f, 0.f);
        float4 acc3 = make_float4(0.f, 0.f, 0.f, 0.f);

        int r = s_lo + rg;
        // branch-free unroll-8: rows r, r+4, ..., r+28, all loads front-batched
        for (; r + 28 < s_hi; r += 32) {
            float4 v0 = __ldcs(&x4[(size_t)(r)      * H4 + c4]);
            float4 v1 = __ldcs(&x4[(size_t)(r + 4)  * H4 + c4]);
            float4 v2 = __ldcs(&x4[(size_t)(r + 8)  * H4 + c4]);
            float4 v3 = __ldcs(&x4[(size_t)(r + 12) * H4 + c4]);
            float4 v4 = __ldcs(&x4[(size_t)(r + 16) * H4 + c4]);
            float4 v5 = __ldcs(&x4[(size_t)(r + 20) * H4 + c4]);
            float4 v6 = __ldcs(&x4[(size_t)(r + 24) * H4 + c4]);
            float4 v7 = __ldcs(&x4[(size_t)(r + 28) * H4 + c4]);
            acc0.x += v0.x; acc0.y += v0.y; acc0.z += v0.z; acc0.w += v0.w;
            acc1.x += v1.x; acc1.y += v1.y; acc1.z += v1.z; acc1.w += v1.w;
            acc2.x += v2.x; acc2.y += v2.y; acc2.z += v2.z; acc2.w += v2.w;
            acc3.x += v3.x; acc3.y += v3.y; acc3.z += v3.z; acc3.w += v3.w;
            acc0.x += v4.x; acc0.y += v4.y; acc0.z += v4.z; acc0.w += v4.w;
            acc1.x += v5.x; acc1.y += v5.y; acc1.z += v5.z; acc1.w += v5.w;
            acc2.x += v6.x; acc2.y += v6.y; acc2.z += v6.z; acc2.w += v6.w;
            acc3.x += v7.x; acc3.y += v7.y; acc3.z += v7.z; acc3.w += v7.w;
        }
        for (; r < s_hi; r += 4) {
            float4 v = __ldcs(&x4[(size_t)r * H4 + c4]);
            acc0.x += v.x; acc0.y += v.y; acc0.z += v.z; acc0.w += v.w;
        }

        acc0.x += acc1.x + acc2.x + acc3.x;
        acc0.y += acc1.y + acc2.y + acc3.y;
        acc0.z += acc1.z + acc2.z + acc3.z;
        acc0.w += acc1.w + acc2.w + acc3.w;

        float* d = &hpool[(size_t)g * HID + c4 * 4];
        atomicAdd(d + 0, acc0.x); atomicAdd(d + 1, acc0.y);
        atomicAdd(d + 2, acc0.z); atomicAdd(d + 3, acc0.w);

        s_lo = s_hi;
    }
}

// ---------------------------------------------------------------------------
// 2) FUSED MLP: phase 1 = gemm1 (h1 = (hpool+vnode)@W1+b1) + BN-stat atomics;
//    grid spin-barrier (all 128 blocks resident); phase 2 = BN scale/shift +
//    gemm2 (vn = relu(h1*scale+shift)@W2 + b2). W2 chunk-0 prefetched
//    before the spin. virtual_node folded into the A-tile load.
// ---------------------------------------------------------------------------
__global__ __launch_bounds__(256) void mlp_kernel(
    const float* __restrict__ A, const float* __restrict__ vnode,
    const float* __restrict__ W1, const float* __restrict__ b1,
    const float* __restrict__ gamma, const float* __restrict__ beta,
    const float* __restrict__ W2, const float* __restrict__ b2,
    float* __restrict__ h1, float* __restrict__ gsum,
    float* __restrict__ gsumsq, int* __restrict__ barrier,
    float* __restrict__ C)
{
    __shared__ float  As[2][32][33];
    __shared__ float4 Bs4[2][32][16];
    __shared__ float  red_s[16][64];
    __shared__ float  red_q[16][64];
    __shared__ float  scale_s[HID];
    __shared__ float  shift_s[HID];

    int t  = threadIdx.x;
    int tx = t & 15, ty = t >> 4;
    int m0 = blockIdx.y * 32;
    int n0 = blockIdx.x * 64;

    int arow = t >> 3, aq = t & 7;     // A: 32 rows x 8 float4
    int brow = t >> 4, bq = t & 15;    // B: 16 rows x 16 float4 (x2)

    // ===================== phase 1: gemm1 =====================
    {
        const float4* Ar = reinterpret_cast<const float4*>(&A[(size_t)(m0 + arow) * HID]);
        const float4* Vr = reinterpret_cast<const float4*>(&vnode[(size_t)(m0 + arow) * HID]);

        float4 a_r  = Ar[aq];
        float4 v_r  = Vr[aq];
        float4 b_r0 = *reinterpret_cast<const float4*>(&W1[(size_t)brow * HID + n0 + bq * 4]);
        float4 b_r1 = *reinterpret_cast<const float4*>(&W1[(size_t)(brow + 16) * HID + n0 + bq * 4]);
        As[0][arow][aq * 4 + 0] = a_r.x + v_r.x;
        As[0][arow][aq * 4 + 1] = a_r.y + v_r.y;
        As[0][arow][aq * 4 + 2] = a_r.z + v_r.z;
        As[0][arow][aq * 4 + 3] = a_r.w + v_r.w;
        Bs4[0][brow][bq]      = b_r0;
        Bs4[0][brow + 16][bq] = b_r1;
        __syncthreads();

        float acc[2][4];
#pragma unroll
        for (int i = 0; i < 2; i++)
#pragma unroll
            for (int j = 0; j < 4; j++) acc[i][j] = 0.f;

#pragma unroll
        for (int it = 0; it < 8; it++) {
            int cur = it & 1;
            if (it < 7) {
                int k1 = (it + 1) * 32;
                a_r  = Ar[(it + 1) * 8 + aq];
                v_r  = Vr[(it + 1) * 8 + aq];
                b_r0 = *reinterpret_cast<const float4*>(&W1[(size_t)(k1 + brow) * HID + n0 + bq * 4]);
                b_r1 = *reinterpret_cast<const float4*>(&W1[(size_t)(k1 + brow + 16) * HID + n0 + bq * 4]);
            }
#pragma unroll
            for (int kk = 0; kk < 32; kk++) {
                float4 bb = Bs4[cur][kk][tx];
                float a0 = As[cur][ty * 2 + 0][kk];
                float a1 = As[cur][ty * 2 + 1][kk];
                acc[0][0] += a0 * bb.x; acc[0][1] += a0 * bb.y; acc[0][2] += a0 * bb.z; acc[0][3] += a0 * bb.w;
                acc[1][0] += a1 * bb.x; acc[1][1] += a1 * bb.y; acc[1][2] += a1 * bb.z; acc[1][3] += a1 * bb.w;
            }
            if (it < 7) {
                int nxt = cur ^ 1;
                As[nxt][arow][aq * 4 + 0] = a_r.x + v_r.x;
                As[nxt][arow][aq * 4 + 1] = a_r.y + v_r.y;
                As[nxt][arow][aq * 4 + 2] = a_r.z + v_r.z;
                As[nxt][arow][aq * 4 + 3] = a_r.w + v_r.w;
                Bs4[nxt][brow][bq]      = b_r0;
                Bs4[nxt][brow + 16][bq] = b_r1;
            }
            __syncthreads();
        }

        float4 bv = *reinterpret_cast<const float4*>(&b1[n0 + tx * 4]);
        float v0[4], v1[4];
        v0[0] = acc[0][0] + bv.x; v0[1] = acc[0][1] + bv.y; v0[2] = acc[0][2] + bv.z; v0[3] = acc[0][3] + bv.w;
        v1[0] = acc[1][0] + bv.x; v1[1] = acc[1][1] + bv.y; v1[2] = acc[1][2] + bv.z; v1[3] = acc[1][3] + bv.w;

        *reinterpret_cast<float4*>(&h1[(size_t)(m0 + ty * 2 + 0) * HID + n0 + tx * 4]) =
            make_float4(v0[0], v0[1], v0[2], v0[3]);
        *reinterpret_cast<float4*>(&h1[(size_t)(m0 + ty * 2 + 1) * HID + n0 + tx * 4]) =
            make_float4(v1[0], v1[1], v1[2], v1[3]);

#pragma unroll
        for (int j = 0; j < 4; j++) {
            red_s[ty][tx * 4 + j] = v0[j] + v1[j];
            red_q[ty][tx * 4 + j] = v0[j] * v0[j] + v1[j] * v1[j];
        }
        __syncthreads();
        if (t < 64) {
            float S = 0.f, Q = 0.f;
#pragma unroll
            for (int g = 0; g < 16; g++) { S += red_s[g][t]; Q += red_q[g][t]; }
            atomicAdd(&gsum[n0 + t],   S);
            atomicAdd(&gsumsq[n0 + t], Q);
        }
    }

    // ================= grid barrier (all blocks resident) =================
    __threadfence();
    __syncthreads();
    if (t == 0) atomicAdd(barrier, 1);

    // prefetch W2 chunk 0 while waiting — independent of the barrier
    float4 b_r0 = *reinterpret_cast<const float4*>(&W2[(size_t)brow * HID + n0 + bq * 4]);
    float4 b_r1 = *reinterpret_cast<const float4*>(&W2[(size_t)(brow + 16) * HID + n0 + bq * 4]);

    if (t == 0) {
        while (*((volatile int*)barrier) < MLP_BLOCKS) { }
    }
    __syncthreads();
    __threadfence();

    // ===================== phase 2: BN + gemm2 =====================
    {
        float mean = gsum[t] * (1.f / NB);
        float var  = gsumsq[t] * (1.f / NB) - mean * mean;
        float sc   = gamma[t] * rsqrtf(var + EPS);
        scale_s[t] = sc;
        shift_s[t] = beta[t] - mean * sc;
    }
    __syncthreads();

    {
        const float4* Ar = reinterpret_cast<const float4*>(&h1[(size_t)(m0 + arow) * HID]);

        float4 a_r = Ar[aq];
        {
            int kc = aq * 4;
            As[0][arow][kc + 0] = fmaxf(a_r.x * scale_s[kc + 0] + shift_s[kc + 0], 0.f);
            As[0][arow][kc + 1] = fmaxf(a_r.y * scale_s[kc + 1] + shift_s[kc + 1], 0.f);
            As[0][arow][kc + 2] = fmaxf(a_r.z * scale_s[kc + 2] + shift_s[kc + 2], 0.f);
            As[0][arow][kc + 3] = fmaxf(a_r.w * scale_s[kc + 3] + shift_s[kc + 3], 0.f);
        }
        Bs4[0][brow][bq]      = b_r0;
        Bs4[0][brow + 16][bq] = b_r1;
        __syncthreads();

        float acc[2][4];
#pragma unroll
        for (int i = 0; i < 2; i++)
#pragma unroll
            for (int j = 0; j < 4; j++) acc[i][j] = 0.f;

#pragma unroll
        for (int it = 0; it < 8; it++) {
            int cur = it & 1;
            if (it < 7) {
                int k1 = (it + 1) * 32;
                a_r  = Ar[(it + 1) * 8 + aq];
                b_r0 = *reinterpret_cast<const float4*>(&W2[(size_t)(k1 + brow) * HID + n0 + bq * 4]);
                b_r1 = *reinterpret_cast<const float4*>(&W2[(size_t)(k1 + brow + 16) * HID + n0 + bq * 4]);
            }
#pragma unroll
            for (int kk = 0; kk < 32; kk++) {
                float4 bb = Bs4[cur][kk][tx];
                float a0 = As[cur][ty * 2 + 0][kk];
                float a1 = As[cur][ty * 2 + 1][kk];
                acc[0][0] += a0 * bb.x; acc[0][1] += a0 * bb.y; acc[0][2] += a0 * bb.z; acc[0][3] += a0 * bb.w;
                acc[1][0] += a1 * bb.x; acc[1][1] += a1 * bb.y; acc[1][2] += a1 * bb.z; acc[1][3] += a1 * bb.w;
            }
            if (it < 7) {
                int nxt = cur ^ 1;
                int kc  = (it + 1) * 32 + aq * 4;
                int sc0 = aq * 4;
                As[nxt][arow][sc0 + 0] = fmaxf(a_r.x * scale_s[kc + 0] + shift_s[kc + 0], 0.f);
                As[nxt][arow][sc0 + 1] = fmaxf(a_r.y * scale_s[kc + 1] + shift_s[kc + 1], 0.f);
                As[nxt][arow][sc0 + 2] = fmaxf(a_r.z * scale_s[kc + 2] + shift_s[kc + 2], 0.f);
                As[nxt][arow][sc0 + 3] = fmaxf(a_r.w * scale_s[kc + 3] + shift_s[kc + 3], 0.f);
                Bs4[nxt][brow][bq]      = b_r0;
                Bs4[nxt][brow + 16][bq] = b_r1;
            }
            __syncthreads();
        }

        float4 bv = *reinterpret_cast<const float4*>(&b2[n0 + tx * 4]);
#pragma unroll
        for (int i = 0; i < 2; i++) {
            float4 o;
            o.x = acc[i][0] + bv.x; o.y = acc[i][1] + bv.y;
            o.z = acc[i][2] + bv.z; o.w = acc[i][3] + bv.w;
            *reinterpret_cast<float4*>(&C[(size_t)(m0 + ty * 2 + i) * HID + n0 + tx * 4]) = o;
        }
    }
}

// ---------------------------------------------------------------------------
// 3) gather broadcast-add: x_out = x + vn[batch_idx].   (unchanged: 85% DRAM)
// ---------------------------------------------------------------------------
__global__ __launch_bounds__(256) void gather_kernel(
    const float* __restrict__ x, const int* __restrict__ bidx,
    const float* __restrict__ vn, float* __restrict__ out, unsigned total4)
{
    const float4* x4  = reinterpret_cast<const float4*>(x);
    const float4* vn4 = reinterpret_cast<const float4*>(vn);
    float4*       o4  = reinterpret_cast<float4*>(out);

    unsigned base = blockIdx.x * 1024u + threadIdx.x;

    if (base + 768u < total4) {
        unsigned i0 = base, i1 = base + 256u, i2 = base + 512u, i3 = base + 768u;

        int g0 = __ldg(&bidx[i0 >> 6]);
        int g1 = __ldg(&bidx[i1 >> 6]);
        int g2 = __ldg(&bidx[i2 >> 6]);
        int g3 = __ldg(&bidx[i3 >> 6]);

        float4 a0 = __ldcs(&x4[i0]);
        float4 a1 = __ldcs(&x4[i1]);
        float4 a2 = __ldcs(&x4[i2]);
        float4 a3 = __ldcs(&x4[i3]);

        float4 v0 = vn4[(unsigned)g0 * H4 + (i0 & 63u)];
        float4 v1 = vn4[(unsigned)g1 * H4 + (i1 & 63u)];
        float4 v2 = vn4[(unsigned)g2 * H4 + (i2 & 63u)];
        float4 v3 = vn4[(unsigned)g3 * H4 + (i3 & 63u)];

        float4 o;
        o.x = a0.x + v0.x; o.y = a0.y + v0.y; o.z = a0.z + v0.z; o.w = a0.w + v0.w;
        __stcs(&o4[i0], o);
        o.x = a1.x + v1.x; o.y = a1.y + v1.y; o.z = a1.z + v1.z; o.w = a1.w + v1.w;
        __stcs(&o4[i1], o);
        o.x = a2.x + v2.x; o.y = a2.y + v2.y; o.z = a2.z + v2.z; o.w = a2.w + v2.w;
        __stcs(&o4[i2], o);
        o.x = a3.x + v3.x; o.y = a3.y + v3.y; o.z = a3.z + v3.z; o.w = a3.w + v3.w;
        __stcs(&o4[i3], o);
    } else {
#pragma unroll
        for (int j = 0; j < 4; j++) {
            unsigned i = base + (unsigned)j * 256u;
            if (i < total4) {
                int g = __ldg(&bidx[i >> 6]);
                float4 a = __ldcs(&x4[i]);
                float4 v = vn4[(unsigned)g * H4 + (i & 63u)];
                float4 o;
                o.x = a.x + v.x; o.y = a.y + v.y; o.z = a.z + v.z; o.w = a.w + v.w;
                __stcs(&o4[i], o);
            }
        }
    }
}

// ---------------------------------------------------------------------------
extern "C" void kernel_launch(void* const* d_in, const int* in_sizes, int n_in,
                              void* d_out, int out_size)
{
    const float* x     = (const float*)d_in[0];
    const int*   bidx  = (const int*)  d_in[1];
    const float* vnode = (const float*)d_in[2];
    const float* W1    = (const float*)d_in[3];
    const float* b1    = (const float*)d_in[4];
    const float* gamma = (const float*)d_in[5];
    const float* beta  = (const float*)d_in[6];
    const float* W2    = (const float*)d_in[7];
    const float* b2    = (const float*)d_in[8];

    int n = in_sizes[0] / HID;             // number of nodes

    float* out   = (float*)d_out;          // x_out: [n, H]
    float* vnout = out + (size_t)n * HID;  // vn: [B, H]

    float* hpool; cudaGetSymbolAddress((void**)&hpool, g_hpool);
    float* h1;    cudaGetSymbolAddress((void**)&h1,    g_h1);
    float* gsum;  cudaGetSymbolAddress((void**)&gsum,  g_sum);
    float* gsq;   cudaGetSymbolAddress((void**)&gsq,   g_sumsq);
    int*   bar;   cudaGetSymbolAddress((void**)&bar,   g_barrier);

    init_kernel<<<NB * HID / 4 / 256, 256>>>(hpool, gsum, gsq, bar);

    pool_kernel<<<POOL_BLOCKS, 256>>>(x, bidx, hpool, n);

    dim3 ggrid(HID / 64, NB / 32);         // (4, 32) = 128 blocks, all resident
    mlp_kernel<<<ggrid, 256>>>(hpool, vnode, W1, b1, gamma, beta, W2, b2,
                               h1, gsum, gsq, bar, vnout);

    unsigned total4 = (unsigned)n * H4;
    int blocks = (int)((total4 + 1023u) / 1024u);
    gather_kernel<<<blocks, 256>>>(x, bidx, vnout, out, total4);
}

// round 12
// speedup vs baseline: 1.0027x; 1.0027x over previous
#include <cuda_runtime.h>
#include <cstdint>

#define HID 256
#define H4  64            // HID/4 float4 per row
#define NB  1024          // number of graphs
#define EPS 1e-5f
#define MLP_BLOCKS 128
#define POOL_BLOCKS 4096

// scratch (allocation-free rule: static __device__ globals)
__device__ float g_hpool[NB * HID];
__device__ float g_h1[NB * HID];
__device__ float g_sum[HID];
__device__ float g_sumsq[HID];
__device__ int   g_barrier;

// ---------------------------------------------------------------------------
// 0) init: zero hpool (atomic accumulation target), BN stats, barrier.
// ---------------------------------------------------------------------------
__global__ __launch_bounds__(256) void init_kernel(
    float* __restrict__ hpool, float* __restrict__ gsum,
    float* __restrict__ gsumsq, int* __restrict__ barrier)
{
    int i = blockIdx.x * 256 + threadIdx.x;
    reinterpret_cast<float4*>(hpool)[i] = make_float4(0.f, 0.f, 0.f, 0.f);
    if (blockIdx.x == 0) {
        gsum[threadIdx.x] = 0.f;
        gsumsq[threadIdx.x] = 0.f;
        if (threadIdx.x == 0) *barrier = 0;
    }
}

// ---------------------------------------------------------------------------
// 1) chunked segmented reduction (pool). Fixed contiguous row chunks per
//    block (fine granularity -> negligible wave tail); each thread owns
//    (column c4, rowgroup rg); accumulates while graph id unchanged,
//    flushes via spread-address atomicAdd on change.
//    Main loop unroll-8 with ALL loads front-batched (MLP~8).
// ---------------------------------------------------------------------------
__global__ __launch_bounds__(256) void pool_kernel(
    const float* __restrict__ x, const int* __restrict__ bidx,
    float* __restrict__ hpool, int n)
{
    int t  = threadIdx.x;
    int c4 = t & 63;        // float4 column 0..63
    int rg = t >> 6;        // row group 0..3

    int chunk = (n + POOL_BLOCKS - 1) / POOL_BLOCKS;
    int r0 = blockIdx.x * chunk;
    int r1 = min(r0 + chunk, n);
    if (r0 >= r1) return;

    const float4* x4 = reinterpret_cast<const float4*>(x);

    int cur = -1;
    float4 acc = make_float4(0.f, 0.f, 0.f, 0.f);

    int r = r0 + rg;

#define POOL_FLUSH()                                            \
    {                                                           \
        float* d = &hpool[(size_t)cur * HID + c4 * 4];          \
        atomicAdd(d + 0, acc.x); atomicAdd(d + 1, acc.y);       \
        atomicAdd(d + 2, acc.z); atomicAdd(d + 3, acc.w);       \
    }
#define POOL_STEP(G, V)                                                        \
    if ((G) != cur) {                                                          \
        if (cur >= 0) POOL_FLUSH();                                            \
        cur = (G); acc = (V);                                                  \
    } else { acc.x += (V).x; acc.y += (V).y; acc.z += (V).z; acc.w += (V).w; }

    // unroll-8 main loop: rows r, r+4, ..., r+28 (all loads front-batched)
    for (; r + 28 < r1; r += 32) {
        int g0 = __ldg(&bidx[r]);
        int g1 = __ldg(&bidx[r + 4]);
        int g2 = __ldg(&bidx[r + 8]);
        int g3 = __ldg(&bidx[r + 12]);
        int g4 = __ldg(&bidx[r + 16]);
        int g5 = __ldg(&bidx[r + 20]);
        int g6 = __ldg(&bidx[r + 24]);
        int g7 = __ldg(&bidx[r + 28]);
        float4 v0 = __ldcs(&x4[(size_t)(r)      * H4 + c4]);
        float4 v1 = __ldcs(&x4[(size_t)(r + 4)  * H4 + c4]);
        float4 v2 = __ldcs(&x4[(size_t)(r + 8)  * H4 + c4]);
        float4 v3 = __ldcs(&x4[(size_t)(r + 12) * H4 + c4]);
        float4 v4 = __ldcs(&x4[(size_t)(r + 16) * H4 + c4]);
        float4 v5 = __ldcs(&x4[(size_t)(r + 20) * H4 + c4]);
        float4 v6 = __ldcs(&x4[(size_t)(r + 24) * H4 + c4]);
        float4 v7 = __ldcs(&x4[(size_t)(r + 28) * H4 + c4]);

        POOL_STEP(g0, v0)
        POOL_STEP(g1, v1)
        POOL_STEP(g2, v2)
        POOL_STEP(g3, v3)
        POOL_STEP(g4, v4)
        POOL_STEP(g5, v5)
        POOL_STEP(g6, v6)
        POOL_STEP(g7, v7)
    }
    // remainder
    for (; r < r1; r += 4) {
        int g = __ldg(&bidx[r]);
        float4 v = __ldcs(&x4[(size_t)r * H4 + c4]);
        POOL_STEP(g, v)
    }
    if (cur >= 0) POOL_FLUSH();
#undef POOL_STEP
#undef POOL_FLUSH
}

// ---------------------------------------------------------------------------
// 2) FUSED MLP: phase 1 = gemm1 (h1 = (hpool+vnode)@W1+b1) + BN-stat atomics;
//    grid spin-barrier (all 128 blocks resident); phase 2 = BN scale/shift +
//    gemm2 (vn = relu(h1*scale+shift)@W2 + b2). W2 chunk-0 prefetched
//    before the spin. virtual_node folded into the A-tile load.
// ---------------------------------------------------------------------------
__global__ __launch_bounds__(256) void mlp_kernel(
    const float* __restrict__ A, const float* __restrict__ vnode,
    const float* __restrict__ W1, const float* __restrict__ b1,
    const float* __restrict__ gamma, const float* __restrict__ beta,
    const float* __restrict__ W2, const float* __restrict__ b2,
    float* __restrict__ h1, float* __restrict__ gsum,
    float* __restrict__ gsumsq, int* __restrict__ barrier,
    float* __restrict__ C)
{
    __shared__ float  As[2][32][33];
    __shared__ float4 Bs4[2][32][16];
    __shared__ float  red_s[16][64];
    __shared__ float  red_q[16][64];
    __shared__ float  scale_s[HID];
    __shared__ float  shift_s[HID];

    int t  = threadIdx.x;
    int tx = t & 15, ty = t >> 4;
    int m0 = blockIdx.y * 32;
    int n0 = blockIdx.x * 64;

    int arow = t >> 3, aq = t & 7;     // A: 32 rows x 8 float4
    int brow = t >> 4, bq = t & 15;    // B: 16 rows x 16 float4 (x2)

    // ===================== phase 1: gemm1 =====================
    {
        const float4* Ar = reinterpret_cast<const float4*>(&A[(size_t)(m0 + arow) * HID]);
        const float4* Vr = reinterpret_cast<const float4*>(&vnode[(size_t)(m0 + arow) * HID]);

        float4 a_r  = Ar[aq];
        float4 v_r  = Vr[aq];
        float4 b_r0 = *reinterpret_cast<const float4*>(&W1[(size_t)brow * HID + n0 + bq * 4]);
        float4 b_r1 = *reinterpret_cast<const float4*>(&W1[(size_t)(brow + 16) * HID + n0 + bq * 4]);
        As[0][arow][aq * 4 + 0] = a_r.x + v_r.x;
        As[0][arow][aq * 4 + 1] = a_r.y + v_r.y;
        As[0][arow][aq * 4 + 2] = a_r.z + v_r.z;
        As[0][arow][aq * 4 + 3] = a_r.w + v_r.w;
        Bs4[0][brow][bq]      = b_r0;
        Bs4[0][brow + 16][bq] = b_r1;
        __syncthreads();

        float acc[2][4];
#pragma unroll
        for (int i = 0; i < 2; i++)
#pragma unroll
            for (int j = 0; j < 4; j++) acc[i][j] = 0.f;

#pragma unroll
        for (int it = 0; it < 8; it++) {
            int cur = it & 1;
            if (it < 7) {
                int k1 = (it + 1) * 32;
                a_r  = Ar[(it + 1) * 8 + aq];
                v_r  = Vr[(it + 1) * 8 + aq];
                b_r0 = *reinterpret_cast<const float4*>(&W1[(size_t)(k1 + brow) * HID + n0 + bq * 4]);
                b_r1 = *reinterpret_cast<const float4*>(&W1[(size_t)(k1 + brow + 16) * HID + n0 + bq * 4]);
            }
#pragma unroll
            for (int kk = 0; kk < 32; kk++) {
                float4 bb = Bs4[cur][kk][tx];
                float a0 = As[cur][ty * 2 + 0][kk];
                float a1 = As[cur][ty * 2 + 1][kk];
                acc[0][0] += a0 * bb.x; acc[0][1] += a0 * bb.y; acc[0][2] += a0 * bb.z; acc[0][3] += a0 * bb.w;
                acc[1][0] += a1 * bb.x; acc[1][1] += a1 * bb.y; acc[1][2] += a1 * bb.z; acc[1][3] += a1 * bb.w;
            }
            if (it < 7) {
                int nxt = cur ^ 1;
                As[nxt][arow][aq * 4 + 0] = a_r.x + v_r.x;
                As[nxt][arow][aq * 4 + 1] = a_r.y + v_r.y;
                As[nxt][arow][aq * 4 + 2] = a_r.z + v_r.z;
                As[nxt][arow][aq * 4 + 3] = a_r.w + v_r.w;
                Bs4[nxt][brow][bq]      = b_r0;
                Bs4[nxt][brow + 16][bq] = b_r1;
            }
            __syncthreads();
        }

        float4 bv = *reinterpret_cast<const float4*>(&b1[n0 + tx * 4]);
        float v0[4], v1[4];
        v0[0] = acc[0][0] + bv.x; v0[1] = acc[0][1] + bv.y; v0[2] = acc[0][2] + bv.z; v0[3] = acc[0][3] + bv.w;
        v1[0] = acc[1][0] + bv.x; v1[1] = acc[1][1] + bv.y; v1[2] = acc[1][2] + bv.z; v1[3] = acc[1][3] + bv.w;

        *reinterpret_cast<float4*>(&h1[(size_t)(m0 + ty * 2 + 0) * HID + n0 + tx * 4]) =
            make_float4(v0[0], v0[1], v0[2], v0[3]);
        *reinterpret_cast<float4*>(&h1[(size_t)(m0 + ty * 2 + 1) * HID + n0 + tx * 4]) =
            make_float4(v1[0], v1[1], v1[2], v1[3]);

#pragma unroll
        for (int j = 0; j < 4; j++) {
            red_s[ty][tx * 4 + j] = v0[j] + v1[j];
            red_q[ty][tx * 4 + j] = v0[j] * v0[j] + v1[j] * v1[j];
        }
        __syncthreads();
        if (t < 64) {
            float S = 0.f, Q = 0.f;
#pragma unroll
            for (int g = 0; g < 16; g++) { S += red_s[g][t]; Q += red_q[g][t]; }
            atomicAdd(&gsum[n0 + t],   S);
            atomicAdd(&gsumsq[n0 + t], Q);
        }
    }

    // ================= grid barrier (all blocks resident) =================
    __threadfence();
    __syncthreads();
    if (t == 0) atomicAdd(barrier, 1);

    // prefetch W2 chunk 0 while waiting — independent of the barrier
    float4 b_r0 = *reinterpret_cast<const float4*>(&W2[(size_t)brow * HID + n0 + bq * 4]);
    float4 b_r1 = *reinterpret_cast<const float4*>(&W2[(size_t)(brow + 16) * HID + n0 + bq * 4]);

    if (t == 0) {
        while (*((volatile int*)barrier) < MLP_BLOCKS) { }
    }
    __syncthreads();
    __threadfence();

    // ===================== phase 2: BN + gemm2 =====================
    {
        float mean = gsum[t] * (1.f / NB);
        float var  = gsumsq[t] * (1.f / NB) - mean * mean;
        float sc   = gamma[t] * rsqrtf(var + EPS);
        scale_s[t] = sc;
        shift_s[t] = beta[t] - mean * sc;
    }
    __syncthreads();

    {
        const float4* Ar = reinterpret_cast<const float4*>(&h1[(size_t)(m0 + arow) * HID]);

        float4 a_r = Ar[aq];
        {
            int kc = aq * 4;
            As[0][arow][kc + 0] = fmaxf(a_r.x * scale_s[kc + 0] + shift_s[kc + 0], 0.f);
            As[0][arow][kc + 1] = fmaxf(a_r.y * scale_s[kc + 1] + shift_s[kc + 1], 0.f);
            As[0][arow][kc + 2] = fmaxf(a_r.z * scale_s[kc + 2] + shift_s[kc + 2], 0.f);
            As[0][arow][kc + 3] = fmaxf(a_r.w * scale_s[kc + 3] + shift_s[kc + 3], 0.f);
        }
        Bs4[0][brow][bq]      = b_r0;
        Bs4[0][brow + 16][bq] = b_r1;
        __syncthreads();

        float acc[2][4];
#pragma unroll
        for (int i = 0; i < 2; i++)
#pragma unroll
            for (int j = 0; j < 4; j++) acc[i][j] = 0.f;

#pragma unroll
        for (int it = 0; it < 8; it++) {
            int cur = it & 1;
            if (it < 7) {
                int k1 = (it + 1) * 32;
                a_r  = Ar[(it + 1) * 8 + aq];
                b_r0 = *reinterpret_cast<const float4*>(&W2[(size_t)(k1 + brow) * HID + n0 + bq * 4]);
                b_r1 = *reinterpret_cast<const float4*>(&W2[(size_t)(k1 + brow + 16) * HID + n0 + bq * 4]);
            }
#pragma unroll
            for (int kk = 0; kk < 32; kk++) {
                float4 bb = Bs4[cur][kk][tx];
                float a0 = As[cur][ty * 2 + 0][kk];
                float a1 = As[cur][ty * 2 + 1][kk];
                acc[0][0] += a0 * bb.x; acc[0][1] += a0 * bb.y; acc[0][2] += a0 * bb.z; acc[0][3] += a0 * bb.w;
                acc[1][0] += a1 * bb.x; acc[1][1] += a1 * bb.y; acc[1][2] += a1 * bb.z; acc[1][3] += a1 * bb.w;
            }
            if (it < 7) {
                int nxt = cur ^ 1;
                int kc  = (it + 1) * 32 + aq * 4;
                int sc0 = aq * 4;
                As[nxt][arow][sc0 + 0] = fmaxf(a_r.x * scale_s[kc + 0] + shift_s[kc + 0], 0.f);
                As[nxt][arow][sc0 + 1] = fmaxf(a_r.y * scale_s[kc + 1] + shift_s[kc + 1], 0.f);
                As[nxt][arow][sc0 + 2] = fmaxf(a_r.z * scale_s[kc + 2] + shift_s[kc + 2], 0.f);
                As[nxt][arow][sc0 + 3] = fmaxf(a_r.w * scale_s[kc + 3] + shift_s[kc + 3], 0.f);
                Bs4[nxt][brow][bq]      = b_r0;
                Bs4[nxt][brow + 16][bq] = b_r1;
            }
            __syncthreads();
        }

        float4 bv = *reinterpret_cast<const float4*>(&b2[n0 + tx * 4]);
#pragma unroll
        for (int i = 0; i < 2; i++) {
            float4 o;
            o.x = acc[i][0] + bv.x; o.y = acc[i][1] + bv.y;
            o.z = acc[i][2] + bv.z; o.w = acc[i][3] + bv.w;
            *reinterpret_cast<float4*>(&C[(size_t)(m0 + ty * 2 + i) * HID + n0 + tx * 4]) = o;
        }
    }
}

// ---------------------------------------------------------------------------
// 3) gather broadcast-add: x_out = x + vn[batch_idx].   (unchanged: 85% DRAM)
// ---------------------------------------------------------------------------
__global__ __launch_bounds__(256) void gather_kernel(
    const float* __restrict__ x, const int* __restrict__ bidx,
    const float* __restrict__ vn, float* __restrict__ out, unsigned total4)
{
    const float4* x4  = reinterpret_cast<const float4*>(x);
    const float4* vn4 = reinterpret_cast<const float4*>(vn);
    float4*       o4  = reinterpret_cast<float4*>(out);

    unsigned base = blockIdx.x * 1024u + threadIdx.x;

    if (base + 768u < total4) {
        unsigned i0 = base, i1 = base + 256u, i2 = base + 512u, i3 = base + 768u;

        int g0 = __ldg(&bidx[i0 >> 6]);
        int g1 = __ldg(&bidx[i1 >> 6]);
        int g2 = __ldg(&bidx[i2 >> 6]);
        int g3 = __ldg(&bidx[i3 >> 6]);

        float4 a0 = __ldcs(&x4[i0]);
        float4 a1 = __ldcs(&x4[i1]);
        float4 a2 = __ldcs(&x4[i2]);
        float4 a3 = __ldcs(&x4[i3]);

        float4 v0 = vn4[(unsigned)g0 * H4 + (i0 & 63u)];
        float4 v1 = vn4[(unsigned)g1 * H4 + (i1 & 63u)];
        float4 v2 = vn4[(unsigned)g2 * H4 + (i2 & 63u)];
        float4 v3 = vn4[(unsigned)g3 * H4 + (i3 & 63u)];

        float4 o;
        o.x = a0.x + v0.x; o.y = a0.y + v0.y; o.z = a0.z + v0.z; o.w = a0.w + v0.w;
        __stcs(&o4[i0], o);
        o.x = a1.x + v1.x; o.y = a1.y + v1.y; o.z = a1.z + v1.z; o.w = a1.w + v1.w;
        __stcs(&o4[i1], o);
        o.x = a2.x + v2.x; o.y = a2.y + v2.y; o.z = a2.z + v2.z; o.w = a2.w + v2.w;
        __stcs(&o4[i2], o);
        o.x = a3.x + v3.x; o.y = a3.y + v3.y; o.z = a3.z + v3.z; o.w = a3.w + v3.w;
        __stcs(&o4[i3], o);
    } else {
#pragma unroll
        for (int j = 0; j < 4; j++) {
            unsigned i = base + (unsigned)j * 256u;
            if (i < total4) {
                int g = __ldg(&bidx[i >> 6]);
                float4 a = __ldcs(&x4[i]);
                float4 v = vn4[(unsigned)g * H4 + (i & 63u)];
                float4 o;
                o.x = a.x + v.x; o.y = a.y + v.y; o.z = a.z + v.z; o.w = a.w + v.w;
                __stcs(&o4[i], o);
            }
        }
    }
}

// ---------------------------------------------------------------------------
extern "C" void kernel_launch(void* const* d_in, const int* in_sizes, int n_in,
                              void* d_out, int out_size)
{
    const float* x     = (const float*)d_in[0];
    const int*   bidx  = (const int*)  d_in[1];
    const float* vnode = (const float*)d_in[2];
    const float* W1    = (const float*)d_in[3];
    const float* b1    = (const float*)d_in[4];
    const float* gamma = (const float*)d_in[5];
    const float* beta  = (const float*)d_in[6];
    const float* W2    = (const float*)d_in[7];
    const float* b2    = (const float*)d_in[8];

    int n = in_sizes[0] / HID;             // number of nodes

    float* out   = (float*)d_out;          // x_out: [n, H]
    float* vnout = out + (size_t)n * HID;  // vn: [B, H]

    float* hpool; cudaGetSymbolAddress((void**)&hpool, g_hpool);
    float* h1;    cudaGetSymbolAddress((void**)&h1,    g_h1);
    float* gsum;  cudaGetSymbolAddress((void**)&gsum,  g_sum);
    float* gsq;   cudaGetSymbolAddress((void**)&gsq,   g_sumsq);
    int*   bar;   cudaGetSymbolAddress((void**)&bar,   g_barrier);

    init_kernel<<<NB * HID / 4 / 256, 256>>>(hpool, gsum, gsq, bar);

    pool_kernel<<<POOL_BLOCKS, 256>>>(x, bidx, hpool, n);

    dim3 ggrid(HID / 64, NB / 32);         // (4, 32) = 128 blocks, all resident
    mlp_kernel<<<ggrid, 256>>>(hpool, vnode, W1, b1, gamma, beta, W2, b2,
                               h1, gsum, gsq, bar, vnout);

    unsigned total4 = (unsigned)n * H4;
    int blocks = (int)((total4 + 1023u) / 1024u);
    gather_kernel<<<blocks, 256>>>(x, bidx, vnout, out, total4);
}

// round 13
// speedup vs baseline: 1.0129x; 1.0102x over previous
#include <cuda_runtime.h>
#include <cstdint>

#define HID 256
#define H4  64            // HID/4 float4 per row
#define NB  1024          // number of graphs
#define EPS 1e-5f
#define MLP_BLOCKS 128
#define POOL_BLOCKS 2048
#define TAIL_CACHED 448   // last pool blocks load x with L2-caching (~112MB)

// scratch (allocation-free rule: static __device__ globals)
__device__ float g_hpool[NB * HID];
__device__ float g_h1[NB * HID];
__device__ float g_sum[HID];
__device__ float g_sumsq[HID];
__device__ int   g_barrier;

// ---------------------------------------------------------------------------
// 0) init: zero hpool (atomic accumulation target), BN stats, barrier.
// ---------------------------------------------------------------------------
__global__ __launch_bounds__(256) void init_kernel(
    float* __restrict__ hpool, float* __restrict__ gsum,
    float* __restrict__ gsumsq, int* __restrict__ barrier)
{
    int i = blockIdx.x * 256 + threadIdx.x;
    reinterpret_cast<float4*>(hpool)[i] = make_float4(0.f, 0.f, 0.f, 0.f);
    if (blockIdx.x == 0) {
        gsum[threadIdx.x] = 0.f;
        gsumsq[threadIdx.x] = 0.f;
        if (threadIdx.x == 0) *barrier = 0;
    }
}

// ---------------------------------------------------------------------------
// 1) chunked segmented reduction (pool). r10 body (best measured).
//    NEW: last TAIL_CACHED blocks (which run in the final wave and own the
//    tail of x) load x with default caching so the tail stays L2-resident
//    for the reversed gather; all other blocks stream with __ldcs.
// ---------------------------------------------------------------------------
__global__ __launch_bounds__(256) void pool_kernel(
    const float* __restrict__ x, const int* __restrict__ bidx,
    float* __restrict__ hpool, int n)
{
    int t  = threadIdx.x;
    int c4 = t & 63;        // float4 column 0..63
    int rg = t >> 6;        // row group 0..3

    int chunk = (n + POOL_BLOCKS - 1) / POOL_BLOCKS;
    int r0 = blockIdx.x * chunk;
    int r1 = min(r0 + chunk, n);
    if (r0 >= r1) return;

    bool cached = (blockIdx.x >= POOL_BLOCKS - TAIL_CACHED);

    const float4* x4 = reinterpret_cast<const float4*>(x);

    int cur = -1;
    float4 acc = make_float4(0.f, 0.f, 0.f, 0.f);

#define POOL_FLUSH()                                            \
    {                                                           \
        float* d = &hpool[(size_t)cur * HID + c4 * 4];          \
        atomicAdd(d + 0, acc.x); atomicAdd(d + 1, acc.y);       \
        atomicAdd(d + 2, acc.z); atomicAdd(d + 3, acc.w);       \
    }
#define POOL_STEP(G, V)                                                        \
    if ((G) != cur) {                                                          \
        if (cur >= 0) POOL_FLUSH();                                            \
        cur = (G); acc = (V);                                                  \
    } else { acc.x += (V).x; acc.y += (V).y; acc.z += (V).z; acc.w += (V).w; }

#define POOL_BODY(LOADX)                                                       \
    {                                                                          \
        int r = r0 + rg;                                                       \
        for (; r + 28 < r1; r += 32) {                                         \
            int g0 = __ldg(&bidx[r]);                                          \
            int g1 = __ldg(&bidx[r + 4]);                                      \
            int g2 = __ldg(&bidx[r + 8]);                                      \
            int g3 = __ldg(&bidx[r + 12]);                                     \
            int g4 = __ldg(&bidx[r + 16]);                                     \
            int g5 = __ldg(&bidx[r + 20]);                                     \
            int g6 = __ldg(&bidx[r + 24]);                                     \
            int g7 = __ldg(&bidx[r + 28]);                                     \
            float4 v0 = LOADX(&x4[(size_t)(r)      * H4 + c4]);                \
            float4 v1 = LOADX(&x4[(size_t)(r + 4)  * H4 + c4]);                \
            float4 v2 = LOADX(&x4[(size_t)(r + 8)  * H4 + c4]);                \
            float4 v3 = LOADX(&x4[(size_t)(r + 12) * H4 + c4]);                \
            float4 v4 = LOADX(&x4[(size_t)(r + 16) * H4 + c4]);                \
            float4 v5 = LOADX(&x4[(size_t)(r + 20) * H4 + c4]);                \
            float4 v6 = LOADX(&x4[(size_t)(r + 24) * H4 + c4]);                \
            float4 v7 = LOADX(&x4[(size_t)(r + 28) * H4 + c4]);                \
            POOL_STEP(g0, v0)                                                  \
            POOL_STEP(g1, v1)                                                  \
            POOL_STEP(g2, v2)                                                  \
            POOL_STEP(g3, v3)                                                  \
            POOL_STEP(g4, v4)                                                  \
            POOL_STEP(g5, v5)                                                  \
            POOL_STEP(g6, v6)                                                  \
            POOL_STEP(g7, v7)                                                  \
        }                                                                      \
        for (; r < r1; r += 4) {                                               \
            int g = __ldg(&bidx[r]);                                           \
            float4 v = LOADX(&x4[(size_t)r * H4 + c4]);                        \
            POOL_STEP(g, v)                                                    \
        }                                                                      \
    }

#define LDSTREAM(P) __ldcs(P)
#define LDCACHE(P)  __ldg(P)

    if (cached) {
        POOL_BODY(LDCACHE)
    } else {
        POOL_BODY(LDSTREAM)
    }
    if (cur >= 0) POOL_FLUSH();

#undef LDSTREAM
#undef LDCACHE
#undef POOL_BODY
#undef POOL_STEP
#undef POOL_FLUSH
}

// ---------------------------------------------------------------------------
// 2) FUSED MLP: phase 1 = gemm1 (h1 = (hpool+vnode)@W1+b1) + BN-stat atomics;
//    grid spin-barrier (all 128 blocks resident); phase 2 = BN scale/shift +
//    gemm2 (vn = relu(h1*scale+shift)@W2 + b2). W2 chunk-0 prefetched
//    before the spin. virtual_node folded into the A-tile load.
// ---------------------------------------------------------------------------
__global__ __launch_bounds__(256) void mlp_kernel(
    const float* __restrict__ A, const float* __restrict__ vnode,
    const float* __restrict__ W1, const float* __restrict__ b1,
    const float* __restrict__ gamma, const float* __restrict__ beta,
    const float* __restrict__ W2, const float* __restrict__ b2,
    float* __restrict__ h1, float* __restrict__ gsum,
    float* __restrict__ gsumsq, int* __restrict__ barrier,
    float* __restrict__ C)
{
    __shared__ float  As[2][32][33];
    __shared__ float4 Bs4[2][32][16];
    __shared__ float  red_s[16][64];
    __shared__ float  red_q[16][64];
    __shared__ float  scale_s[HID];
    __shared__ float  shift_s[HID];

    int t  = threadIdx.x;
    int tx = t & 15, ty = t >> 4;
    int m0 = blockIdx.y * 32;
    int n0 = blockIdx.x * 64;

    int arow = t >> 3, aq = t & 7;     // A: 32 rows x 8 float4
    int brow = t >> 4, bq = t & 15;    // B: 16 rows x 16 float4 (x2)

    // ===================== phase 1: gemm1 =====================
    {
        const float4* Ar = reinterpret_cast<const float4*>(&A[(size_t)(m0 + arow) * HID]);
        const float4* Vr = reinterpret_cast<const float4*>(&vnode[(size_t)(m0 + arow) * HID]);

        float4 a_r  = Ar[aq];
        float4 v_r  = Vr[aq];
        float4 b_r0 = *reinterpret_cast<const float4*>(&W1[(size_t)brow * HID + n0 + bq * 4]);
        float4 b_r1 = *reinterpret_cast<const float4*>(&W1[(size_t)(brow + 16) * HID + n0 + bq * 4]);
        As[0][arow][aq * 4 + 0] = a_r.x + v_r.x;
        As[0][arow][aq * 4 + 1] = a_r.y + v_r.y;
        As[0][arow][aq * 4 + 2] = a_r.z + v_r.z;
        As[0][arow][aq * 4 + 3] = a_r.w + v_r.w;
        Bs4[0][brow][bq]      = b_r0;
        Bs4[0][brow + 16][bq] = b_r1;
        __syncthreads();

        float acc[2][4];
#pragma unroll
        for (int i = 0; i < 2; i++)
#pragma unroll
            for (int j = 0; j < 4; j++) acc[i][j] = 0.f;

#pragma unroll
        for (int it = 0; it < 8; it++) {
            int cur = it & 1;
            if (it < 7) {
                int k1 = (it + 1) * 32;
                a_r  = Ar[(it + 1) * 8 + aq];
                v_r  = Vr[(it + 1) * 8 + aq];
                b_r0 = *reinterpret_cast<const float4*>(&W1[(size_t)(k1 + brow) * HID + n0 + bq * 4]);
                b_r1 = *reinterpret_cast<const float4*>(&W1[(size_t)(k1 + brow + 16) * HID + n0 + bq * 4]);
            }
#pragma unroll
            for (int kk = 0; kk < 32; kk++) {
                float4 bb = Bs4[cur][kk][tx];
                float a0 = As[cur][ty * 2 + 0][kk];
                float a1 = As[cur][ty * 2 + 1][kk];
                acc[0][0] += a0 * bb.x; acc[0][1] += a0 * bb.y; acc[0][2] += a0 * bb.z; acc[0][3] += a0 * bb.w;
                acc[1][0] += a1 * bb.x; acc[1][1] += a1 * bb.y; acc[1][2] += a1 * bb.z; acc[1][3] += a1 * bb.w;
            }
            if (it < 7) {
                int nxt = cur ^ 1;
                As[nxt][arow][aq * 4 + 0] = a_r.x + v_r.x;
                As[nxt][arow][aq * 4 + 1] = a_r.y + v_r.y;
                As[nxt][arow][aq * 4 + 2] = a_r.z + v_r.z;
                As[nxt][arow][aq * 4 + 3] = a_r.w + v_r.w;
                Bs4[nxt][brow][bq]      = b_r0;
                Bs4[nxt][brow + 16][bq] = b_r1;
            }
            __syncthreads();
        }

        float4 bv = *reinterpret_cast<const float4*>(&b1[n0 + tx * 4]);
        float v0[4], v1[4];
        v0[0] = acc[0][0] + bv.x; v0[1] = acc[0][1] + bv.y; v0[2] = acc[0][2] + bv.z; v0[3] = acc[0][3] + bv.w;
        v1[0] = acc[1][0] + bv.x; v1[1] = acc[1][1] + bv.y; v1[2] = acc[1][2] + bv.z; v1[3] = acc[1][3] + bv.w;

        *reinterpret_cast<float4*>(&h1[(size_t)(m0 + ty * 2 + 0) * HID + n0 + tx * 4]) =
            make_float4(v0[0], v0[1], v0[2], v0[3]);
        *reinterpret_cast<float4*>(&h1[(size_t)(m0 + ty * 2 + 1) * HID + n0 + tx * 4]) =
            make_float4(v1[0], v1[1], v1[2], v1[3]);

#pragma unroll
        for (int j = 0; j < 4; j++) {
            red_s[ty][tx * 4 + j] = v0[j] + v1[j];
            red_q[ty][tx * 4 + j] = v0[j] * v0[j] + v1[j] * v1[j];
        }
        __syncthreads();
        if (t < 64) {
            float S = 0.f, Q = 0.f;
#pragma unroll
            for (int g = 0; g < 16; g++) { S += red_s[g][t]; Q += red_q[g][t]; }
            atomicAdd(&gsum[n0 + t],   S);
            atomicAdd(&gsumsq[n0 + t], Q);
        }
    }

    // ================= grid barrier (all blocks resident) =================
    __threadfence();
    __syncthreads();
    if (t == 0) atomicAdd(barrier, 1);

    // prefetch W2 chunk 0 while waiting — independent of the barrier
    float4 b_r0 = *reinterpret_cast<const float4*>(&W2[(size_t)brow * HID + n0 + bq * 4]);
    float4 b_r1 = *reinterpret_cast<const float4*>(&W2[(size_t)(brow + 16) * HID + n0 + bq * 4]);

    if (t == 0) {
        while (*((volatile int*)barrier) < MLP_BLOCKS) { }
    }
    __syncthreads();
    __threadfence();

    // ===================== phase 2: BN + gemm2 =====================
    {
        float mean = gsum[t] * (1.f / NB);
        float var  = gsumsq[t] * (1.f / NB) - mean * mean;
        float sc   = gamma[t] * rsqrtf(var + EPS);
        scale_s[t] = sc;
        shift_s[t] = beta[t] - mean * sc;
    }
    __syncthreads();

    {
        const float4* Ar = reinterpret_cast<const float4*>(&h1[(size_t)(m0 + arow) * HID]);

        float4 a_r = Ar[aq];
        {
            int kc = aq * 4;
            As[0][arow][kc + 0] = fmaxf(a_r.x * scale_s[kc + 0] + shift_s[kc + 0], 0.f);
            As[0][arow][kc + 1] = fmaxf(a_r.y * scale_s[kc + 1] + shift_s[kc + 1], 0.f);
            As[0][arow][kc + 2] = fmaxf(a_r.z * scale_s[kc + 2] + shift_s[kc + 2], 0.f);
            As[0][arow][kc + 3] = fmaxf(a_r.w * scale_s[kc + 3] + shift_s[kc + 3], 0.f);
        }
        Bs4[0][brow][bq]      = b_r0;
        Bs4[0][brow + 16][bq] = b_r1;
        __syncthreads();

        float acc[2][4];
#pragma unroll
        for (int i = 0; i < 2; i++)
#pragma unroll
            for (int j = 0; j < 4; j++) acc[i][j] = 0.f;

#pragma unroll
        for (int it = 0; it < 8; it++) {
            int cur = it & 1;
            if (it < 7) {
                int k1 = (it + 1) * 32;
                a_r  = Ar[(it + 1) * 8 + aq];
                b_r0 = *reinterpret_cast<const float4*>(&W2[(size_t)(k1 + brow) * HID + n0 + bq * 4]);
                b_r1 = *reinterpret_cast<const float4*>(&W2[(size_t)(k1 + brow + 16) * HID + n0 + bq * 4]);
            }
#pragma unroll
            for (int kk = 0; kk < 32; kk++) {
                float4 bb = Bs4[cur][kk][tx];
                float a0 = As[cur][ty * 2 + 0][kk];
                float a1 = As[cur][ty * 2 + 1][kk];
                acc[0][0] += a0 * bb.x; acc[0][1] += a0 * bb.y; acc[0][2] += a0 * bb.z; acc[0][3] += a0 * bb.w;
                acc[1][0] += a1 * bb.x; acc[1][1] += a1 * bb.y; acc[1][2] += a1 * bb.z; acc[1][3] += a1 * bb.w;
            }
            if (it < 7) {
                int nxt = cur ^ 1;
                int kc  = (it + 1) * 32 + aq * 4;
                int sc0 = aq * 4;
                As[nxt][arow][sc0 + 0] = fmaxf(a_r.x * scale_s[kc + 0] + shift_s[kc + 0], 0.f);
                As[nxt][arow][sc0 + 1] = fmaxf(a_r.y * scale_s[kc + 1] + shift_s[kc + 1], 0.f);
                As[nxt][arow][sc0 + 2] = fmaxf(a_r.z * scale_s[kc + 2] + shift_s[kc + 2], 0.f);
                As[nxt][arow][sc0 + 3] = fmaxf(a_r.w * scale_s[kc + 3] + shift_s[kc + 3], 0.f);
                Bs4[nxt][brow][bq]      = b_r0;
                Bs4[nxt][brow + 16][bq] = b_r1;
            }
            __syncthreads();
        }

        float4 bv = *reinterpret_cast<const float4*>(&b2[n0 + tx * 4]);
#pragma unroll
        for (int i = 0; i < 2; i++) {
            float4 o;
            o.x = acc[i][0] + bv.x; o.y = acc[i][1] + bv.y;
            o.z = acc[i][2] + bv.z; o.w = acc[i][3] + bv.w;
            *reinterpret_cast<float4*>(&C[(size_t)(m0 + ty * 2 + i) * HID + n0 + tx * 4]) = o;
        }
    }
}

// ---------------------------------------------------------------------------
// 3) gather broadcast-add: x_out = x + vn[batch_idx]. Same body as the
//    verified 85%-DRAM version, but blocks iterate in REVERSE order so the
//    first-running blocks consume the x tail that pool left in L2.
// ---------------------------------------------------------------------------
__global__ __launch_bounds__(256) void gather_kernel(
    const float* __restrict__ x, const int* __restrict__ bidx,
    const float* __restrict__ vn, float* __restrict__ out, unsigned total4)
{
    const float4* x4  = reinterpret_cast<const float4*>(x);
    const float4* vn4 = reinterpret_cast<const float4*>(vn);
    float4*       o4  = reinterpret_cast<float4*>(out);

    unsigned rblk = gridDim.x - 1u - blockIdx.x;      // reversed chunk index
    unsigned base = rblk * 1024u + threadIdx.x;

    if (base + 768u < total4) {
        unsigned i0 = base, i1 = base + 256u, i2 = base + 512u, i3 = base + 768u;

        int g0 = __ldg(&bidx[i0 >> 6]);
        int g1 = __ldg(&bidx[i1 >> 6]);
        int g2 = __ldg(&bidx[i2 >> 6]);
        int g3 = __ldg(&bidx[i3 >> 6]);

        float4 a0 = __ldcs(&x4[i0]);
        float4 a1 = __ldcs(&x4[i1]);
        float4 a2 = __ldcs(&x4[i2]);
        float4 a3 = __ldcs(&x4[i3]);

        float4 v0 = vn4[(unsigned)g0 * H4 + (i0 & 63u)];
        float4 v1 = vn4[(unsigned)g1 * H4 + (i1 & 63u)];
        float4 v2 = vn4[(unsigned)g2 * H4 + (i2 & 63u)];
        float4 v3 = vn4[(unsigned)g3 * H4 + (i3 & 63u)];

        float4 o;
        o.x = a0.x + v0.x; o.y = a0.y + v0.y; o.z = a0.z + v0.z; o.w = a0.w + v0.w;
        __stcs(&o4[i0], o);
        o.x = a1.x + v1.x; o.y = a1.y + v1.y; o.z = a1.z + v1.z; o.w = a1.w + v1.w;
        __stcs(&o4[i1], o);
        o.x = a2.x + v2.x; o.y = a2.y + v2.y; o.z = a2.z + v2.z; o.w = a2.w + v2.w;
        __stcs(&o4[i2], o);
        o.x = a3.x + v3.x; o.y = a3.y + v3.y; o.z = a3.z + v3.z; o.w = a3.w + v3.w;
        __stcs(&o4[i3], o);
    } else {
#pragma unroll
        for (int j = 0; j < 4; j++) {
            unsigned i = base + (unsigned)j * 256u;
            if (i < total4) {
                int g = __ldg(&bidx[i >> 6]);
                float4 a = __ldcs(&x4[i]);
                float4 v = vn4[(unsigned)g * H4 + (i & 63u)];
                float4 o;
                o.x = a.x + v.x; o.y = a.y + v.y; o.z = a.z + v.z; o.w = a.w + v.w;
                __stcs(&o4[i], o);
            }
        }
    }
}

// ---------------------------------------------------------------------------
extern "C" void kernel_launch(void* const* d_in, const int* in_sizes, int n_in,
                              void* d_out, int out_size)
{
    const float* x     = (const float*)d_in[0];
    const int*   bidx  = (const int*)  d_in[1];
    const float* vnode = (const float*)d_in[2];
    const float* W1    = (const float*)d_in[3];
    const float* b1    = (const float*)d_in[4];
    const float* gamma = (const float*)d_in[5];
    const float* beta  = (const float*)d_in[6];
    const float* W2    = (const float*)d_in[7];
    const float* b2    = (const float*)d_in[8];

    int n = in_sizes[0] / HID;             // number of nodes

    float* out   = (float*)d_out;          // x_out: [n, H]
    float* vnout = out + (size_t)n * HID;  // vn: [B, H]

    float* hpool; cudaGetSymbolAddress((void**)&hpool, g_hpool);
    float* h1;    cudaGetSymbolAddress((void**)&h1,    g_h1);
    float* gsum;  cudaGetSymbolAddress((void**)&gsum,  g_sum);
    float* gsq;   cudaGetSymbolAddress((void**)&gsq,   g_sumsq);
    int*   bar;   cudaGetSymbolAddress((void**)&bar,   g_barrier);

    init_kernel<<<NB * HID / 4 / 256, 256>>>(hpool, gsum, gsq, bar);

    pool_kernel<<<POOL_BLOCKS, 256>>>(x, bidx, hpool, n);

    dim3 ggrid(HID / 64, NB / 32);         // (4, 32) = 128 blocks, all resident
    mlp_kernel<<<ggrid, 256>>>(hpool, vnode, W1, b1, gamma, beta, W2, b2,
                               h1, gsum, gsq, bar, vnout);

    unsigned total4 = (unsigned)n * H4;
    int blocks = (int)((total4 + 1023u) / 1024u);
    gather_kernel<<<blocks, 256>>>(x, bidx, vnout, out, total4);
}

// round 14
// speedup vs baseline: 1.0179x; 1.0049x over previous
#include <cuda_runtime.h>
#include <cstdint>

#define HID 256
#define H4  64            // HID/4 float4 per row
#define NB  1024          // number of graphs
#define EPS 1e-5f
#define MLP_BLOCKS 128
#define POOL_BLOCKS 2048
#define TAIL_CACHED 448   // last pool blocks load x with L2-caching (~112MB)

// scratch (allocation-free rule: static __device__ globals; zero-initialized
// at module load; each call's gather re-zeroes them for the next call)
__device__ float g_hpool[NB * HID];
__device__ float g_h1[NB * HID];
__device__ float g_sum[HID];
__device__ float g_sumsq[HID];
__device__ int   g_barrier;

// ---------------------------------------------------------------------------
// 1) chunked segmented reduction (pool). r10 body (best measured).
//    Last TAIL_CACHED blocks load x with default caching (L2 handoff to the
//    reversed gather); all other blocks stream with __ldcs.
// ---------------------------------------------------------------------------
__global__ __launch_bounds__(256) void pool_kernel(
    const float* __restrict__ x, const int* __restrict__ bidx,
    float* __restrict__ hpool, int n)
{
    int t  = threadIdx.x;
    int c4 = t & 63;        // float4 column 0..63
    int rg = t >> 6;        // row group 0..3

    int chunk = (n + POOL_BLOCKS - 1) / POOL_BLOCKS;
    int r0 = blockIdx.x * chunk;
    int r1 = min(r0 + chunk, n);
    if (r0 >= r1) return;

    bool cached = (blockIdx.x >= POOL_BLOCKS - TAIL_CACHED);

    const float4* x4 = reinterpret_cast<const float4*>(x);

    int cur = -1;
    float4 acc = make_float4(0.f, 0.f, 0.f, 0.f);

#define POOL_FLUSH()                                            \
    {                                                           \
        float* d = &hpool[(size_t)cur * HID + c4 * 4];          \
        atomicAdd(d + 0, acc.x); atomicAdd(d + 1, acc.y);       \
        atomicAdd(d + 2, acc.z); atomicAdd(d + 3, acc.w);       \
    }
#define POOL_STEP(G, V)                                                        \
    if ((G) != cur) {                                                          \
        if (cur >= 0) POOL_FLUSH();                                            \
        cur = (G); acc = (V);                                                  \
    } else { acc.x += (V).x; acc.y += (V).y; acc.z += (V).z; acc.w += (V).w; }

#define POOL_BODY(LOADX)                                                       \
    {                                                                          \
        int r = r0 + rg;                                                       \
        for (; r + 28 < r1; r += 32) {                                         \
            int g0 = __ldg(&bidx[r]);                                          \
            int g1 = __ldg(&bidx[r + 4]);                                      \
            int g2 = __ldg(&bidx[r + 8]);                                      \
            int g3 = __ldg(&bidx[r + 12]);                                     \
            int g4 = __ldg(&bidx[r + 16]);                                     \
            int g5 = __ldg(&bidx[r + 20]);                                     \
            int g6 = __ldg(&bidx[r + 24]);                                     \
            int g7 = __ldg(&bidx[r + 28]);                                     \
            float4 v0 = LOADX(&x4[(size_t)(r)      * H4 + c4]);                \
            float4 v1 = LOADX(&x4[(size_t)(r + 4)  * H4 + c4]);                \
            float4 v2 = LOADX(&x4[(size_t)(r + 8)  * H4 + c4]);                \
            float4 v3 = LOADX(&x4[(size_t)(r + 12) * H4 + c4]);                \
            float4 v4 = LOADX(&x4[(size_t)(r + 16) * H4 + c4]);                \
            float4 v5 = LOADX(&x4[(size_t)(r + 20) * H4 + c4]);                \
            float4 v6 = LOADX(&x4[(size_t)(r + 24) * H4 + c4]);                \
            float4 v7 = LOADX(&x4[(size_t)(r + 28) * H4 + c4]);                \
            POOL_STEP(g0, v0)                                                  \
            POOL_STEP(g1, v1)                                                  \
            POOL_STEP(g2, v2)                                                  \
            POOL_STEP(g3, v3)                                                  \
            POOL_STEP(g4, v4)                                                  \
            POOL_STEP(g5, v5)                                                  \
            POOL_STEP(g6, v6)                                                  \
            POOL_STEP(g7, v7)                                                  \
        }                                                                      \
        for (; r < r1; r += 4) {                                               \
            int g = __ldg(&bidx[r]);                                           \
            float4 v = LOADX(&x4[(size_t)r * H4 + c4]);                        \
            POOL_STEP(g, v)                                                    \
        }                                                                      \
    }

#define LDSTREAM(P) __ldcs(P)
#define LDCACHE(P)  __ldg(P)

    if (cached) {
        POOL_BODY(LDCACHE)
    } else {
        POOL_BODY(LDSTREAM)
    }
    if (cur >= 0) POOL_FLUSH();

#undef LDSTREAM
#undef LDCACHE
#undef POOL_BODY
#undef POOL_STEP
#undef POOL_FLUSH
}

// ---------------------------------------------------------------------------
// 2) FUSED MLP: phase 1 = gemm1 (h1 = (hpool+vnode)@W1+b1) + BN-stat atomics;
//    grid spin-barrier (all 128 blocks resident); phase 2 = BN scale/shift +
//    gemm2 (vn = relu(h1*scale+shift)@W2 + b2). W2 chunk-0 prefetched
//    before the spin. virtual_node folded into the A-tile load.
// ---------------------------------------------------------------------------
__global__ __launch_bounds__(256) void mlp_kernel(
    const float* __restrict__ A, const float* __restrict__ vnode,
    const float* __restrict__ W1, const float* __restrict__ b1,
    const float* __restrict__ gamma, const float* __restrict__ beta,
    const float* __restrict__ W2, const float* __restrict__ b2,
    float* __restrict__ h1, float* __restrict__ gsum,
    float* __restrict__ gsumsq, int* __restrict__ barrier,
    float* __restrict__ C)
{
    __shared__ float  As[2][32][33];
    __shared__ float4 Bs4[2][32][16];
    __shared__ float  red_s[16][64];
    __shared__ float  red_q[16][64];
    __shared__ float  scale_s[HID];
    __shared__ float  shift_s[HID];

    int t  = threadIdx.x;
    int tx = t & 15, ty = t >> 4;
    int m0 = blockIdx.y * 32;
    int n0 = blockIdx.x * 64;

    int arow = t >> 3, aq = t & 7;     // A: 32 rows x 8 float4
    int brow = t >> 4, bq = t & 15;    // B: 16 rows x 16 float4 (x2)

    // ===================== phase 1: gemm1 =====================
    {
        const float4* Ar = reinterpret_cast<const float4*>(&A[(size_t)(m0 + arow) * HID]);
        const float4* Vr = reinterpret_cast<const float4*>(&vnode[(size_t)(m0 + arow) * HID]);

        float4 a_r  = Ar[aq];
        float4 v_r  = Vr[aq];
        float4 b_r0 = *reinterpret_cast<const float4*>(&W1[(size_t)brow * HID + n0 + bq * 4]);
        float4 b_r1 = *reinterpret_cast<const float4*>(&W1[(size_t)(brow + 16) * HID + n0 + bq * 4]);
        As[0][arow][aq * 4 + 0] = a_r.x + v_r.x;
        As[0][arow][aq * 4 + 1] = a_r.y + v_r.y;
        As[0][arow][aq * 4 + 2] = a_r.z + v_r.z;
        As[0][arow][aq * 4 + 3] = a_r.w + v_r.w;
        Bs4[0][brow][bq]      = b_r0;
        Bs4[0][brow + 16][bq] = b_r1;
        __syncthreads();

        float acc[2][4];
#pragma unroll
        for (int i = 0; i < 2; i++)
#pragma unroll
            for (int j = 0; j < 4; j++) acc[i][j] = 0.f;

#pragma unroll
        for (int it = 0; it < 8; it++) {
            int cur = it & 1;
            if (it < 7) {
                int k1 = (it + 1) * 32;
                a_r  = Ar[(it + 1) * 8 + aq];
                v_r  = Vr[(it + 1) * 8 + aq];
                b_r0 = *reinterpret_cast<const float4*>(&W1[(size_t)(k1 + brow) * HID + n0 + bq * 4]);
                b_r1 = *reinterpret_cast<const float4*>(&W1[(size_t)(k1 + brow + 16) * HID + n0 + bq * 4]);
            }
#pragma unroll
            for (int kk = 0; kk < 32; kk++) {
                float4 bb = Bs4[cur][kk][tx];
                float a0 = As[cur][ty * 2 + 0][kk];
                float a1 = As[cur][ty * 2 + 1][kk];
                acc[0][0] += a0 * bb.x; acc[0][1] += a0 * bb.y; acc[0][2] += a0 * bb.z; acc[0][3] += a0 * bb.w;
                acc[1][0] += a1 * bb.x; acc[1][1] += a1 * bb.y; acc[1][2] += a1 * bb.z; acc[1][3] += a1 * bb.w;
            }
            if (it < 7) {
                int nxt = cur ^ 1;
                As[nxt][arow][aq * 4 + 0] = a_r.x + v_r.x;
                As[nxt][arow][aq * 4 + 1] = a_r.y + v_r.y;
                As[nxt][arow][aq * 4 + 2] = a_r.z + v_r.z;
                As[nxt][arow][aq * 4 + 3] = a_r.w + v_r.w;
                Bs4[nxt][brow][bq]      = b_r0;
                Bs4[nxt][brow + 16][bq] = b_r1;
            }
            __syncthreads();
        }

        float4 bv = *reinterpret_cast<const float4*>(&b1[n0 + tx * 4]);
        float v0[4], v1[4];
        v0[0] = acc[0][0] + bv.x; v0[1] = acc[0][1] + bv.y; v0[2] = acc[0][2] + bv.z; v0[3] = acc[0][3] + bv.w;
        v1[0] = acc[1][0] + bv.x; v1[1] = acc[1][1] + bv.y; v1[2] = acc[1][2] + bv.z; v1[3] = acc[1][3] + bv.w;

        *reinterpret_cast<float4*>(&h1[(size_t)(m0 + ty * 2 + 0) * HID + n0 + tx * 4]) =
            make_float4(v0[0], v0[1], v0[2], v0[3]);
        *reinterpret_cast<float4*>(&h1[(size_t)(m0 + ty * 2 + 1) * HID + n0 + tx * 4]) =
            make_float4(v1[0], v1[1], v1[2], v1[3]);

#pragma unroll
        for (int j = 0; j < 4; j++) {
            red_s[ty][tx * 4 + j] = v0[j] + v1[j];
            red_q[ty][tx * 4 + j] = v0[j] * v0[j] + v1[j] * v1[j];
        }
        __syncthreads();
        if (t < 64) {
            float S = 0.f, Q = 0.f;
#pragma unroll
            for (int g = 0; g < 16; g++) { S += red_s[g][t]; Q += red_q[g][t]; }
            atomicAdd(&gsum[n0 + t],   S);
            atomicAdd(&gsumsq[n0 + t], Q);
        }
    }

    // ================= grid barrier (all blocks resident) =================
    __threadfence();
    __syncthreads();
    if (t == 0) atomicAdd(barrier, 1);

    // prefetch W2 chunk 0 while waiting — independent of the barrier
    float4 b_r0 = *reinterpret_cast<const float4*>(&W2[(size_t)brow * HID + n0 + bq * 4]);
    float4 b_r1 = *reinterpret_cast<const float4*>(&W2[(size_t)(brow + 16) * HID + n0 + bq * 4]);

    if (t == 0) {
        while (*((volatile int*)barrier) < MLP_BLOCKS) { }
    }
    __syncthreads();
    __threadfence();

    // ===================== phase 2: BN + gemm2 =====================
    {
        float mean = gsum[t] * (1.f / NB);
        float var  = gsumsq[t] * (1.f / NB) - mean * mean;
        float sc   = gamma[t] * rsqrtf(var + EPS);
        scale_s[t] = sc;
        shift_s[t] = beta[t] - mean * sc;
    }
    __syncthreads();

    {
        const float4* Ar = reinterpret_cast<const float4*>(&h1[(size_t)(m0 + arow) * HID]);

        float4 a_r = Ar[aq];
        {
            int kc = aq * 4;
            As[0][arow][kc + 0] = fmaxf(a_r.x * scale_s[kc + 0] + shift_s[kc + 0], 0.f);
            As[0][arow][kc + 1] = fmaxf(a_r.y * scale_s[kc + 1] + shift_s[kc + 1], 0.f);
            As[0][arow][kc + 2] = fmaxf(a_r.z * scale_s[kc + 2] + shift_s[kc + 2], 0.f);
            As[0][arow][kc + 3] = fmaxf(a_r.w * scale_s[kc + 3] + shift_s[kc + 3], 0.f);
        }
        Bs4[0][brow][bq]      = b_r0;
        Bs4[0][brow + 16][bq] = b_r1;
        __syncthreads();

        float acc[2][4];
#pragma unroll
        for (int i = 0; i < 2; i++)
#pragma unroll
            for (int j = 0; j < 4; j++) acc[i][j] = 0.f;

#pragma unroll
        for (int it = 0; it < 8; it++) {
            int cur = it & 1;
            if (it < 7) {
                int k1 = (it + 1) * 32;
                a_r  = Ar[(it + 1) * 8 + aq];
                b_r0 = *reinterpret_cast<const float4*>(&W2[(size_t)(k1 + brow) * HID + n0 + bq * 4]);
                b_r1 = *reinterpret_cast<const float4*>(&W2[(size_t)(k1 + brow + 16) * HID + n0 + bq * 4]);
            }
#pragma unroll
            for (int kk = 0; kk < 32; kk++) {
                float4 bb = Bs4[cur][kk][tx];
                float a0 = As[cur][ty * 2 + 0][kk];
                float a1 = As[cur][ty * 2 + 1][kk];
                acc[0][0] += a0 * bb.x; acc[0][1] += a0 * bb.y; acc[0][2] += a0 * bb.z; acc[0][3] += a0 * bb.w;
                acc[1][0] += a1 * bb.x; acc[1][1] += a1 * bb.y; acc[1][2] += a1 * bb.z; acc[1][3] += a1 * bb.w;
            }
            if (it < 7) {
                int nxt = cur ^ 1;
                int kc  = (it + 1) * 32 + aq * 4;
                int sc0 = aq * 4;
                As[nxt][arow][sc0 + 0] = fmaxf(a_r.x * scale_s[kc + 0] + shift_s[kc + 0], 0.f);
                As[nxt][arow][sc0 + 1] = fmaxf(a_r.y * scale_s[kc + 1] + shift_s[kc + 1], 0.f);
                As[nxt][arow][sc0 + 2] = fmaxf(a_r.z * scale_s[kc + 2] + shift_s[kc + 2], 0.f);
                As[nxt][arow][sc0 + 3] = fmaxf(a_r.w * scale_s[kc + 3] + shift_s[kc + 3], 0.f);
                Bs4[nxt][brow][bq]      = b_r0;
                Bs4[nxt][brow + 16][bq] = b_r1;
            }
            __syncthreads();
        }

        float4 bv = *reinterpret_cast<const float4*>(&b2[n0 + tx * 4]);
#pragma unroll
        for (int i = 0; i < 2; i++) {
            float4 o;
            o.x = acc[i][0] + bv.x; o.y = acc[i][1] + bv.y;
            o.z = acc[i][2] + bv.z; o.w = acc[i][3] + bv.w;
            *reinterpret_cast<float4*>(&C[(size_t)(m0 + ty * 2 + i) * HID + n0 + tx * 4]) = o;
        }
    }
}

// ---------------------------------------------------------------------------
// 3) gather broadcast-add: x_out = x + vn[batch_idx]. Reversed block order
//    (L2 handoff from pool tail). ALSO amortizes next-call cleanup:
//      blocks 0..255: each thread zeroes one float4 of hpool (1MB total)
//      block 256:     zeroes gsum/gsumsq
//      block 257:     resets the mlp grid-barrier counter
//    Stream-ordered after mlp (which consumed them) and before next call's
//    pool — deterministic every call; statics start zeroed at module load.
// ---------------------------------------------------------------------------
__global__ __launch_bounds__(256) void gather_kernel(
    const float* __restrict__ x, const int* __restrict__ bidx,
    const float* __restrict__ vn, float* __restrict__ out,
    float* __restrict__ hpool, float* __restrict__ gsum,
    float* __restrict__ gsumsq, int* __restrict__ barrier,
    unsigned total4)
{
    // amortized cleanup for the next call
    if (blockIdx.x < 256u) {
        reinterpret_cast<float4*>(hpool)[blockIdx.x * 256u + threadIdx.x] =
            make_float4(0.f, 0.f, 0.f, 0.f);
    } else if (blockIdx.x == 256u) {
        gsum[threadIdx.x] = 0.f;
        gsumsq[threadIdx.x] = 0.f;
    } else if (blockIdx.x == 257u && threadIdx.x == 0u) {
        *barrier = 0;
    }

    const float4* x4  = reinterpret_cast<const float4*>(x);
    const float4* vn4 = reinterpret_cast<const float4*>(vn);
    float4*       o4  = reinterpret_cast<float4*>(out);

    unsigned rblk = gridDim.x - 1u - blockIdx.x;      // reversed chunk index
    unsigned base = rblk * 1024u + threadIdx.x;

    if (base + 768u < total4) {
        unsigned i0 = base, i1 = base + 256u, i2 = base + 512u, i3 = base + 768u;

        int g0 = __ldg(&bidx[i0 >> 6]);
        int g1 = __ldg(&bidx[i1 >> 6]);
        int g2 = __ldg(&bidx[i2 >> 6]);
        int g3 = __ldg(&bidx[i3 >> 6]);

        float4 a0 = __ldcs(&x4[i0]);
        float4 a1 = __ldcs(&x4[i1]);
        float4 a2 = __ldcs(&x4[i2]);
        float4 a3 = __ldcs(&x4[i3]);

        float4 v0 = vn4[(unsigned)g0 * H4 + (i0 & 63u)];
        float4 v1 = vn4[(unsigned)g1 * H4 + (i1 & 63u)];
        float4 v2 = vn4[(unsigned)g2 * H4 + (i2 & 63u)];
        float4 v3 = vn4[(unsigned)g3 * H4 + (i3 & 63u)];

        float4 o;
        o.x = a0.x + v0.x; o.y = a0.y + v0.y; o.z = a0.z + v0.z; o.w = a0.w + v0.w;
        __stcs(&o4[i0], o);
        o.x = a1.x + v1.x; o.y = a1.y + v1.y; o.z = a1.z + v1.z; o.w = a1.w + v1.w;
        __stcs(&o4[i1], o);
        o.x = a2.x + v2.x; o.y = a2.y + v2.y; o.z = a2.z + v2.z; o.w = a2.w + v2.w;
        __stcs(&o4[i2], o);
        o.x = a3.x + v3.x; o.y = a3.y + v3.y; o.z = a3.z + v3.z; o.w = a3.w + v3.w;
        __stcs(&o4[i3], o);
    } else {
#pragma unroll
        for (int j = 0; j < 4; j++) {
            unsigned i = base + (unsigned)j * 256u;
            if (i < total4) {
                int g = __ldg(&bidx[i >> 6]);
                float4 a = __ldcs(&x4[i]);
                float4 v = vn4[(unsigned)g * H4 + (i & 63u)];
                float4 o;
                o.x = a.x + v.x; o.y = a.y + v.y; o.z = a.z + v.z; o.w = a.w + v.w;
                __stcs(&o4[i], o);
            }
        }
    }
}

// ---------------------------------------------------------------------------
extern "C" void kernel_launch(void* const* d_in, const int* in_sizes, int n_in,
                              void* d_out, int out_size)
{
    const float* x     = (const float*)d_in[0];
    const int*   bidx  = (const int*)  d_in[1];
    const float* vnode = (const float*)d_in[2];
    const float* W1    = (const float*)d_in[3];
    const float* b1    = (const float*)d_in[4];
    const float* gamma = (const float*)d_in[5];
    const float* beta  = (const float*)d_in[6];
    const float* W2    = (const float*)d_in[7];
    const float* b2    = (const float*)d_in[8];

    int n = in_sizes[0] / HID;             // number of nodes

    float* out   = (float*)d_out;          // x_out: [n, H]
    float* vnout = out + (size_t)n * HID;  // vn: [B, H]

    float* hpool; cudaGetSymbolAddress((void**)&hpool, g_hpool);
    float* h1;    cudaGetSymbolAddress((void**)&h1,    g_h1);
    float* gsum;  cudaGetSymbolAddress((void**)&gsum,  g_sum);
    float* gsq;   cudaGetSymbolAddress((void**)&gsq,   g_sumsq);
    int*   bar;   cudaGetSymbolAddress((void**)&bar,   g_barrier);

    pool_kernel<<<POOL_BLOCKS, 256>>>(x, bidx, hpool, n);

    dim3 ggrid(HID / 64, NB / 32);         // (4, 32) = 128 blocks, all resident
    mlp_kernel<<<ggrid, 256>>>(hpool, vnode, W1, b1, gamma, beta, W2, b2,
                               h1, gsum, gsq, bar, vnout);

    unsigned total4 = (unsigned)n * H4;
    int blocks = (int)((total4 + 1023u) / 1024u);
    gather_kernel<<<blocks, 256>>>(x, bidx, vnout, out,
                                   hpool, gsum, gsq, bar, total4);
}